// round 2
// baseline (speedup 1.0000x reference)
#include <cuda_runtime.h>
#include <math.h>

#define N_NODES 100000
#define N_EDGES 1600000

// ---------------- scratch (static device globals; no allocations) ----------
__device__ float4 g_basis[N_EDGES];              // 4 tensor-product basis vals / edge
__device__ int4   g_meta[N_EDGES];               // {src, dst, packed wi, 0}
__device__ float  g_deg[N_NODES];
__device__ float  g_deginv[N_NODES];
__device__ float4 g_agg[N_NODES * 4];            // [N][16] accumulators
__device__ float4 g_h1[N_NODES * 4];             // hidden ping
__device__ float4 g_h2[N_NODES * 4];             // hidden pong
__device__ float4 g_xw[N_NODES * 100];           // [N][25][16] = XW precompute (160MB)

// ---------------- kernels --------------------------------------------------

__global__ void zero_kernel() {
    int i = blockIdx.x * blockDim.x + threadIdx.x;
    if (i < N_NODES * 4) g_agg[i] = make_float4(0.f, 0.f, 0.f, 0.f);
    if (i < N_NODES)     g_deg[i] = 0.f;
}

// basis/knot precompute + degree count (shared across all 3 layers)
__global__ void prep_kernel(const float2* __restrict__ attr,
                            const int* __restrict__ src,
                            const int* __restrict__ dst) {
    int e = blockIdx.x * blockDim.x + threadIdx.x;
    if (e >= N_EDGES) return;
    float2 a = attr[e];
    float v0 = a.x * 4.f, v1 = a.y * 4.f;
    float k0f = fminf(fmaxf(floorf(v0), 0.f), 3.f);
    float k1f = fminf(fmaxf(floorf(v1), 0.f), 3.f);
    float f0 = v0 - k0f, f1 = v1 - k1f;
    int k0 = (int)k0f, k1 = (int)k1f;
    float4 b;
    b.x = (1.f - f0) * (1.f - f1);   // (s0,s1)=(0,0)
    b.y = (1.f - f0) * f1;           // (0,1)
    b.z = f0 * (1.f - f1);           // (1,0)
    b.w = f0 * f1;                   // (1,1)
    g_basis[e] = b;
    int j = k0 + 5 * k1;
    int d = dst[e];
    g_meta[e] = make_int4(src[e], d, j | ((j + 5) << 8) | ((j + 1) << 16) | ((j + 6) << 24), 0);
    atomicAdd(&g_deg[d], 1.f);
}

__global__ void recip_kernel() {
    int n = blockIdx.x * blockDim.x + threadIdx.x;
    if (n < N_NODES) g_deginv[n] = 1.f / fmaxf(g_deg[n], 1.f);
}

__device__ __forceinline__ void red_add_v4(float* p, float4 v) {
    asm volatile("red.global.add.v4.f32 [%0], {%1,%2,%3,%4};"
                 :: "l"(p), "f"(v.x), "f"(v.y), "f"(v.z), "f"(v.w) : "memory");
}

// Layer 1 edge kernel: in=2, W1 (25x2x16 = 3.2KB) in shared; 1 thread/edge.
__global__ void edge1_kernel(const float2* __restrict__ x,
                             const float* __restrict__ W1) {
    __shared__ float4 Wsh[200];                  // [25][2][4] float4
    for (int j = threadIdx.x; j < 200; j += blockDim.x)
        Wsh[j] = ((const float4*)W1)[j];
    __syncthreads();
    int e = blockIdx.x * blockDim.x + threadIdx.x;
    if (e >= N_EDGES) return;
    int4 m = g_meta[e];
    float4 b = g_basis[e];
    float2 xv = x[m.x];
    float bs[4] = {b.x, b.y, b.z, b.w};
    float4 acc[4];
#pragma unroll
    for (int l = 0; l < 4; l++) acc[l] = make_float4(0.f, 0.f, 0.f, 0.f);
#pragma unroll
    for (int q = 0; q < 4; q++) {
        int w = (m.z >> (8 * q)) & 0xff;
        float c0 = bs[q] * xv.x, c1 = bs[q] * xv.y;
#pragma unroll
        for (int l = 0; l < 4; l++) {
            float4 w0 = Wsh[w * 8 + l];
            float4 w1 = Wsh[w * 8 + 4 + l];
            acc[l].x += c0 * w0.x + c1 * w1.x;
            acc[l].y += c0 * w0.y + c1 * w1.y;
            acc[l].z += c0 * w0.z + c1 * w1.z;
            acc[l].w += c0 * w0.w + c1 * w1.w;
        }
    }
    float* ap = (float*)&g_agg[(size_t)m.y * 4];
#pragma unroll
    for (int l = 0; l < 4; l++) red_add_v4(ap + l * 4, acc[l]);
}

// XW precompute: block = 128 threads, 100 active as (k,o4); W column register-
// resident (16 float4 / thread), h chunk (100 nodes) staged in shared.
__global__ void xw_kernel(const float4* __restrict__ hin,
                          const float* __restrict__ W) {
    __shared__ float4 hs[400];                   // 100 nodes x 16 floats
    int t = threadIdx.x;
    int n0 = blockIdx.x * 100;
    int k = t >> 2, o4 = t & 3;
    float4 wc[16];
    if (t < 100) {
        const float4* Wv = (const float4*)W;     // [25][16][4]
#pragma unroll
        for (int i = 0; i < 16; i++) wc[i] = Wv[(k * 16 + i) * 4 + o4];
    }
    for (int j = t; j < 400; j += blockDim.x) hs[j] = hin[n0 * 4 + j];
    __syncthreads();
    if (t >= 100) return;
    const float* hsf = (const float*)hs;
    for (int n = 0; n < 100; n++) {
        float4 a = make_float4(0.f, 0.f, 0.f, 0.f);
#pragma unroll
        for (int i = 0; i < 16; i++) {
            float hv = hsf[n * 16 + i];          // warp-broadcast LDS
            a.x += hv * wc[i].x; a.y += hv * wc[i].y;
            a.z += hv * wc[i].z; a.w += hv * wc[i].w;
        }
        g_xw[((size_t)(n0 + n) * 25 + k) * 4 + o4] = a;
    }
}

// Edge gather for layers 2/3: 1 thread/edge; 4 random 64B XW gathers,
// weighted sum, 4 vectorized reductions into agg.
__global__ void edge_gather_kernel() {
    int e = blockIdx.x * blockDim.x + threadIdx.x;
    if (e >= N_EDGES) return;
    int4 m = g_meta[e];
    float4 b = g_basis[e];
    float bs[4] = {b.x, b.y, b.z, b.w};
    size_t base = (size_t)m.x * 100;
    float4 acc[4];
#pragma unroll
    for (int l = 0; l < 4; l++) acc[l] = make_float4(0.f, 0.f, 0.f, 0.f);
#pragma unroll
    for (int q = 0; q < 4; q++) {
        int w = (m.z >> (8 * q)) & 0xff;
        const float4* p = &g_xw[base + w * 4];
        float4 v0 = p[0], v1 = p[1], v2 = p[2], v3 = p[3];
        float s = bs[q];
        acc[0].x += s * v0.x; acc[0].y += s * v0.y; acc[0].z += s * v0.z; acc[0].w += s * v0.w;
        acc[1].x += s * v1.x; acc[1].y += s * v1.y; acc[1].z += s * v1.z; acc[1].w += s * v1.w;
        acc[2].x += s * v2.x; acc[2].y += s * v2.y; acc[2].z += s * v2.z; acc[2].w += s * v2.w;
        acc[3].x += s * v3.x; acc[3].y += s * v3.y; acc[3].z += s * v3.z; acc[3].w += s * v3.w;
    }
    float* ap = (float*)&g_agg[(size_t)m.y * 4];
#pragma unroll
    for (int l = 0; l < 4; l++) red_add_v4(ap + l * 4, acc[l]);
}

// Node update, layer 1 (root: 2x16): h = relu(agg/deg + x@root + b); zero agg.
__global__ void node1_kernel(const float2* __restrict__ x,
                             const float* __restrict__ root,
                             const float* __restrict__ bias,
                             float4* __restrict__ hout) {
    __shared__ float4 rsh[8];                    // [2][4]
    __shared__ float4 bsh[4];
    if (threadIdx.x < 8)  rsh[threadIdx.x] = ((const float4*)root)[threadIdx.x];
    if (threadIdx.x < 4)  bsh[threadIdx.x] = ((const float4*)bias)[threadIdx.x];
    __syncthreads();
    int n = blockIdx.x * blockDim.x + threadIdx.x;
    if (n >= N_NODES) return;
    float di = g_deginv[n];
    float2 xv = x[n];
    float4* ag = &g_agg[(size_t)n * 4];
    float4* ho = &hout[(size_t)n * 4];
#pragma unroll
    for (int l = 0; l < 4; l++) {
        float4 a = ag[l];
        float4 r0 = rsh[l], r1 = rsh[4 + l], bb = bsh[l];
        float4 o;
        o.x = fmaxf(bb.x + a.x * di + xv.x * r0.x + xv.y * r1.x, 0.f);
        o.y = fmaxf(bb.y + a.y * di + xv.x * r0.y + xv.y * r1.y, 0.f);
        o.z = fmaxf(bb.z + a.z * di + xv.x * r0.z + xv.y * r1.z, 0.f);
        o.w = fmaxf(bb.w + a.w * di + xv.x * r0.w + xv.y * r1.w, 0.f);
        ho[l] = o;
        ag[l] = make_float4(0.f, 0.f, 0.f, 0.f);
    }
}

// Node update, 16-channel root; 1 thread/node.
__global__ void node16_kernel(const float4* __restrict__ hin,
                              const float* __restrict__ root,
                              const float* __restrict__ bias,
                              float4* __restrict__ hout) {
    __shared__ float4 rsh[64];                   // [16][4]
    __shared__ float4 bsh[4];
    for (int j = threadIdx.x; j < 64; j += blockDim.x)
        rsh[j] = ((const float4*)root)[j];
    if (threadIdx.x < 4) bsh[threadIdx.x] = ((const float4*)bias)[threadIdx.x];
    __syncthreads();
    int n = blockIdx.x * blockDim.x + threadIdx.x;
    if (n >= N_NODES) return;
    float di = g_deginv[n];
    float4* ag = &g_agg[(size_t)n * 4];
    const float4* hp = &hin[(size_t)n * 4];
    float4 h[4];
#pragma unroll
    for (int l = 0; l < 4; l++) h[l] = hp[l];
    const float* hf = (const float*)h;
    float4 acc[4];
#pragma unroll
    for (int l = 0; l < 4; l++) {
        float4 a = ag[l];
        float4 bb = bsh[l];
        acc[l].x = bb.x + a.x * di; acc[l].y = bb.y + a.y * di;
        acc[l].z = bb.z + a.z * di; acc[l].w = bb.w + a.w * di;
        ag[l] = make_float4(0.f, 0.f, 0.f, 0.f);
    }
#pragma unroll
    for (int i = 0; i < 16; i++) {
        float hv = hf[i];
#pragma unroll
        for (int l = 0; l < 4; l++) {
            float4 r = rsh[i * 4 + l];           // same addr all lanes -> broadcast
            acc[l].x += hv * r.x; acc[l].y += hv * r.y;
            acc[l].z += hv * r.z; acc[l].w += hv * r.w;
        }
    }
    float4* ho = &hout[(size_t)n * 4];
#pragma unroll
    for (int l = 0; l < 4; l++) {
        acc[l].x = fmaxf(acc[l].x, 0.f); acc[l].y = fmaxf(acc[l].y, 0.f);
        acc[l].z = fmaxf(acc[l].z, 0.f); acc[l].w = fmaxf(acc[l].w, 0.f);
        ho[l] = acc[l];
    }
}

__global__ void final_kernel(const float4* __restrict__ hin,
                             const float* __restrict__ fcw,
                             const float* __restrict__ fcb,
                             float* __restrict__ out) {
    int n = blockIdx.x * blockDim.x + threadIdx.x;
    if (n >= N_NODES) return;
    const float4* h = hin + (size_t)n * 4;
    const float4* w = (const float4*)fcw;
    float z = fcb[0];
#pragma unroll
    for (int j = 0; j < 4; j++) {
        float4 hv = h[j], wv = w[j];
        z += hv.x * wv.x + hv.y * wv.y + hv.z * wv.z + hv.w * wv.w;
    }
    out[n] = 1.f / (1.f + expf(-z));
}

// ---------------- launch ---------------------------------------------------

extern "C" void kernel_launch(void* const* d_in, const int* in_sizes, int n_in,
                              void* d_out, int out_size) {
    const float2* x     = (const float2*)d_in[0];
    const int*    ei    = (const int*)d_in[1];
    const float2* attr  = (const float2*)d_in[2];
    const float*  W1    = (const float*)d_in[3];
    const float*  root1 = (const float*)d_in[4];
    const float*  b1    = (const float*)d_in[5];
    const float*  W2    = (const float*)d_in[6];
    const float*  root2 = (const float*)d_in[7];
    const float*  b2    = (const float*)d_in[8];
    const float*  W3    = (const float*)d_in[9];
    const float*  root3 = (const float*)d_in[10];
    const float*  b3    = (const float*)d_in[11];
    const float*  fcw   = (const float*)d_in[12];
    const float*  fcb   = (const float*)d_in[13];
    const int* src = ei;
    const int* dst = ei + N_EDGES;

    float4 *h1, *h2;
    cudaGetSymbolAddress((void**)&h1, g_h1);
    cudaGetSymbolAddress((void**)&h2, g_h2);

    const int TB = 256;
    int gZero  = (N_NODES * 4 + TB - 1) / TB;
    int gEdge  = (N_EDGES + TB - 1) / TB;
    int gNode  = (N_NODES + TB - 1) / TB;

    zero_kernel<<<gZero, TB>>>();
    prep_kernel<<<gEdge, TB>>>(attr, src, dst);
    recip_kernel<<<gNode, TB>>>();

    // layer 1 (in=2)
    edge1_kernel<<<gEdge, TB>>>(x, W1);
    node1_kernel<<<gNode, TB>>>(x, root1, b1, h1);

    // layer 2
    xw_kernel<<<N_NODES / 100, 128>>>(h1, W2);
    edge_gather_kernel<<<gEdge, TB>>>();
    node16_kernel<<<gNode, TB>>>(h1, root2, b2, h2);

    // layer 3
    xw_kernel<<<N_NODES / 100, 128>>>(h2, W3);
    edge_gather_kernel<<<gEdge, TB>>>();
    node16_kernel<<<gNode, TB>>>(h2, root3, b3, h1);

    final_kernel<<<gNode, TB>>>(h1, fcw, fcb, (float*)d_out);
}

// round 3
// speedup vs baseline: 1.5820x; 1.5820x over previous
#include <cuda_runtime.h>
#include <math.h>

#define N_NODES 100000
#define N_EDGES 1600000
#define FULL 0xffffffffu

// ---------------- scratch (static device globals; no allocations) ----------
__device__ float4 g_basis[N_EDGES];              // 4 tensor-product basis vals / edge
__device__ int4   g_meta[N_EDGES];               // {src, dst, packed wi, 0}
__device__ float  g_deg[N_NODES];
__device__ float  g_deginv[N_NODES];
__device__ float4 g_agg[N_NODES * 4];            // [N][16] accumulators
__device__ float4 g_h1[N_NODES * 4];             // hidden ping
__device__ float4 g_h2[N_NODES * 4];             // hidden pong
__device__ float4 g_xw[N_NODES * 100];           // [N][25][16] = XW precompute (160MB)

// ---------------- kernels --------------------------------------------------

__global__ void zero_kernel() {
    int i = blockIdx.x * blockDim.x + threadIdx.x;
    if (i < N_NODES * 4) g_agg[i] = make_float4(0.f, 0.f, 0.f, 0.f);
    if (i < N_NODES)     g_deg[i] = 0.f;
}

// basis/knot precompute + degree count (shared across all 3 layers)
__global__ void prep_kernel(const float2* __restrict__ attr,
                            const int* __restrict__ src,
                            const int* __restrict__ dst) {
    int e = blockIdx.x * blockDim.x + threadIdx.x;
    if (e >= N_EDGES) return;
    float2 a = attr[e];
    float v0 = a.x * 4.f, v1 = a.y * 4.f;
    float k0f = fminf(fmaxf(floorf(v0), 0.f), 3.f);
    float k1f = fminf(fmaxf(floorf(v1), 0.f), 3.f);
    float f0 = v0 - k0f, f1 = v1 - k1f;
    int k0 = (int)k0f, k1 = (int)k1f;
    float4 b;
    b.x = (1.f - f0) * (1.f - f1);   // (s0,s1)=(0,0)
    b.y = (1.f - f0) * f1;           // (0,1)
    b.z = f0 * (1.f - f1);           // (1,0)
    b.w = f0 * f1;                   // (1,1)
    g_basis[e] = b;
    int j = k0 + 5 * k1;
    int d = dst[e];
    g_meta[e] = make_int4(src[e], d, j | ((j + 5) << 8) | ((j + 1) << 16) | ((j + 6) << 24), 0);
    atomicAdd(&g_deg[d], 1.f);
}

__global__ void recip_kernel() {
    int n = blockIdx.x * blockDim.x + threadIdx.x;
    if (n < N_NODES) g_deginv[n] = 1.f / fmaxf(g_deg[n], 1.f);
}

__device__ __forceinline__ void red_add_v4(float* p, float4 v) {
    asm volatile("red.global.add.v4.f32 [%0], {%1,%2,%3,%4};"
                 :: "l"(p), "f"(v.x), "f"(v.y), "f"(v.z), "f"(v.w) : "memory");
}

// Layer 1 edge kernel: in=2, 4 threads/edge (lane l = out cols 4l..4l+3).
// Shared W row stride padded to 9 float4 so bank group = (w + l) mod 8
// (kills the deterministic 8-way conflict of stride 8).
// Metadata: thread t = e*4+l loads exactly component l of meta/basis
// (fully coalesced), quads exchange via shuffles.
__global__ void edge1_kernel(const float2* __restrict__ x,
                             const float* __restrict__ W1) {
    __shared__ float4 Wsh[25 * 9];               // padded rows
    for (int j = threadIdx.x; j < 200; j += blockDim.x)
        Wsh[(j >> 3) * 9 + (j & 7)] = ((const float4*)W1)[j];
    __syncthreads();
    int t = blockIdx.x * blockDim.x + threadIdx.x;   // E*4 threads exactly
    int lane = threadIdx.x & 31;
    int qb = lane & ~3;                          // quad base lane
    int l = lane & 3;
    int mc = ((const int*)g_meta)[t];            // component l of my edge
    float bc = ((const float*)g_basis)[t];
    int s  = __shfl_sync(FULL, mc, qb + 0);
    int d  = __shfl_sync(FULL, mc, qb + 1);
    int wi = __shfl_sync(FULL, mc, qb + 2);
    float bs0 = __shfl_sync(FULL, bc, qb + 0);
    float bs1 = __shfl_sync(FULL, bc, qb + 1);
    float bs2 = __shfl_sync(FULL, bc, qb + 2);
    float bs3 = __shfl_sync(FULL, bc, qb + 3);
    float bs[4] = {bs0, bs1, bs2, bs3};
    float2 xv = x[s];
    float4 acc = make_float4(0.f, 0.f, 0.f, 0.f);
#pragma unroll
    for (int q = 0; q < 4; q++) {
        int w = (wi >> (8 * q)) & 0xff;
        float4 w0 = Wsh[w * 9 + l];
        float4 w1 = Wsh[w * 9 + 4 + l];
        float c0 = bs[q] * xv.x, c1 = bs[q] * xv.y;
        acc.x += c0 * w0.x + c1 * w1.x;
        acc.y += c0 * w0.y + c1 * w1.y;
        acc.z += c0 * w0.z + c1 * w1.z;
        acc.w += c0 * w0.w + c1 * w1.w;
    }
    red_add_v4((float*)&g_agg[(size_t)d * 4 + l], acc);
}

// XW precompute: block = 128 threads, 100 active as (k,o4); W column register-
// resident (16 float4 / thread), h chunk (100 nodes) staged in shared.
__global__ void xw_kernel(const float4* __restrict__ hin,
                          const float* __restrict__ W) {
    __shared__ float4 hs[400];                   // 100 nodes x 16 floats
    int t = threadIdx.x;
    int n0 = blockIdx.x * 100;
    int k = t >> 2, o4 = t & 3;
    float4 wc[16];
    if (t < 100) {
        const float4* Wv = (const float4*)W;     // [25][16][4]
#pragma unroll
        for (int i = 0; i < 16; i++) wc[i] = Wv[(k * 16 + i) * 4 + o4];
    }
    for (int j = t; j < 400; j += blockDim.x) hs[j] = hin[n0 * 4 + j];
    __syncthreads();
    if (t >= 100) return;
    const float* hsf = (const float*)hs;
    for (int n = 0; n < 100; n++) {
        float4 a = make_float4(0.f, 0.f, 0.f, 0.f);
#pragma unroll
        for (int i = 0; i < 16; i++) {
            float hv = hsf[n * 16 + i];          // warp-broadcast LDS
            a.x += hv * wc[i].x; a.y += hv * wc[i].y;
            a.z += hv * wc[i].z; a.w += hv * wc[i].w;
        }
        g_xw[((size_t)(n0 + n) * 25 + k) * 4 + o4] = a;
    }
}

// Edge gather for layers 2/3: 4 threads/edge; per tap the quad loads one
// contiguous 64B row of XW; metadata coalesced via shuffles.
__global__ void edge_gather_kernel() {
    int t = blockIdx.x * blockDim.x + threadIdx.x;
    int lane = threadIdx.x & 31;
    int qb = lane & ~3;
    int l = lane & 3;
    int mc = ((const int*)g_meta)[t];
    float bc = ((const float*)g_basis)[t];
    int s  = __shfl_sync(FULL, mc, qb + 0);
    int d  = __shfl_sync(FULL, mc, qb + 1);
    int wi = __shfl_sync(FULL, mc, qb + 2);
    float bs0 = __shfl_sync(FULL, bc, qb + 0);
    float bs1 = __shfl_sync(FULL, bc, qb + 1);
    float bs2 = __shfl_sync(FULL, bc, qb + 2);
    float bs3 = __shfl_sync(FULL, bc, qb + 3);
    float bs[4] = {bs0, bs1, bs2, bs3};
    size_t base = (size_t)s * 100;
    float4 acc = make_float4(0.f, 0.f, 0.f, 0.f);
#pragma unroll
    for (int q = 0; q < 4; q++) {
        int w = (wi >> (8 * q)) & 0xff;
        float4 v = g_xw[base + w * 4 + l];
        acc.x += bs[q] * v.x; acc.y += bs[q] * v.y;
        acc.z += bs[q] * v.z; acc.w += bs[q] * v.w;
    }
    red_add_v4((float*)&g_agg[(size_t)d * 4 + l], acc);
}

// Node update, layer 1 (root: 2x16): h = relu(agg/deg + x@root + b); zero agg.
// 4 threads/node, lane l = out cols 4l..4l+3 (coalesced agg access).
__global__ void node1_kernel(const float2* __restrict__ x,
                             const float* __restrict__ root,
                             const float* __restrict__ bias,
                             float4* __restrict__ hout) {
    __shared__ float4 rsh[8];                    // [2][4]
    __shared__ float4 bsh[4];
    if (threadIdx.x < 8)  rsh[threadIdx.x] = ((const float4*)root)[threadIdx.x];
    if (threadIdx.x < 4)  bsh[threadIdx.x] = ((const float4*)bias)[threadIdx.x];
    __syncthreads();
    int t = blockIdx.x * blockDim.x + threadIdx.x;
    int n = t >> 2;
    if (n >= N_NODES) return;
    int l = t & 3;
    float4 a = g_agg[(size_t)n * 4 + l];
    float di = g_deginv[n];
    float2 xv = x[n];
    float4 r0 = rsh[l], r1 = rsh[4 + l], bb = bsh[l];
    float4 o;
    o.x = fmaxf(bb.x + a.x * di + xv.x * r0.x + xv.y * r1.x, 0.f);
    o.y = fmaxf(bb.y + a.y * di + xv.x * r0.y + xv.y * r1.y, 0.f);
    o.z = fmaxf(bb.z + a.z * di + xv.x * r0.z + xv.y * r1.z, 0.f);
    o.w = fmaxf(bb.w + a.w * di + xv.x * r0.w + xv.y * r1.w, 0.f);
    hout[(size_t)n * 4 + l] = o;
    g_agg[(size_t)n * 4 + l] = make_float4(0.f, 0.f, 0.f, 0.f);
}

// Node update, 16-channel root; 4 threads/node.
__global__ void node16_kernel(const float4* __restrict__ hin,
                              const float* __restrict__ root,
                              const float* __restrict__ bias,
                              float4* __restrict__ hout) {
    __shared__ float4 rsh[64];                   // [16][4]
    __shared__ float4 bsh[4];
    for (int j = threadIdx.x; j < 64; j += blockDim.x)
        rsh[j] = ((const float4*)root)[j];
    if (threadIdx.x < 4) bsh[threadIdx.x] = ((const float4*)bias)[threadIdx.x];
    __syncthreads();
    int t = blockIdx.x * blockDim.x + threadIdx.x;
    int n = t >> 2;
    if (n >= N_NODES) return;
    int l = t & 3;
    float4 a = g_agg[(size_t)n * 4 + l];
    float di = g_deginv[n];
    float4 acc = bsh[l];
    acc.x += a.x * di; acc.y += a.y * di; acc.z += a.z * di; acc.w += a.w * di;
    const float* h = (const float*)(hin + (size_t)n * 4);
#pragma unroll
    for (int i = 0; i < 16; i++) {
        float hv = h[i];
        float4 r = rsh[i * 4 + l];
        acc.x += hv * r.x; acc.y += hv * r.y; acc.z += hv * r.z; acc.w += hv * r.w;
    }
    acc.x = fmaxf(acc.x, 0.f); acc.y = fmaxf(acc.y, 0.f);
    acc.z = fmaxf(acc.z, 0.f); acc.w = fmaxf(acc.w, 0.f);
    hout[(size_t)n * 4 + l] = acc;
    g_agg[(size_t)n * 4 + l] = make_float4(0.f, 0.f, 0.f, 0.f);
}

__global__ void final_kernel(const float4* __restrict__ hin,
                             const float* __restrict__ fcw,
                             const float* __restrict__ fcb,
                             float* __restrict__ out) {
    int n = blockIdx.x * blockDim.x + threadIdx.x;
    if (n >= N_NODES) return;
    const float4* h = hin + (size_t)n * 4;
    const float4* w = (const float4*)fcw;
    float z = fcb[0];
#pragma unroll
    for (int j = 0; j < 4; j++) {
        float4 hv = h[j], wv = w[j];
        z += hv.x * wv.x + hv.y * wv.y + hv.z * wv.z + hv.w * wv.w;
    }
    out[n] = 1.f / (1.f + expf(-z));
}

// ---------------- launch ---------------------------------------------------

extern "C" void kernel_launch(void* const* d_in, const int* in_sizes, int n_in,
                              void* d_out, int out_size) {
    const float2* x     = (const float2*)d_in[0];
    const int*    ei    = (const int*)d_in[1];
    const float2* attr  = (const float2*)d_in[2];
    const float*  W1    = (const float*)d_in[3];
    const float*  root1 = (const float*)d_in[4];
    const float*  b1    = (const float*)d_in[5];
    const float*  W2    = (const float*)d_in[6];
    const float*  root2 = (const float*)d_in[7];
    const float*  b2    = (const float*)d_in[8];
    const float*  W3    = (const float*)d_in[9];
    const float*  root3 = (const float*)d_in[10];
    const float*  b3    = (const float*)d_in[11];
    const float*  fcw   = (const float*)d_in[12];
    const float*  fcb   = (const float*)d_in[13];
    const int* src = ei;
    const int* dst = ei + N_EDGES;

    float4 *h1, *h2;
    cudaGetSymbolAddress((void**)&h1, g_h1);
    cudaGetSymbolAddress((void**)&h2, g_h2);

    const int TB = 256;
    int gZero  = (N_NODES * 4 + TB - 1) / TB;
    int gEdge  = (N_EDGES + TB - 1) / TB;
    int gEdge4 = (N_EDGES * 4) / TB;             // exact: 25000
    int gNode4 = (N_NODES * 4 + TB - 1) / TB;
    int gNode  = (N_NODES + TB - 1) / TB;

    zero_kernel<<<gZero, TB>>>();
    prep_kernel<<<gEdge, TB>>>(attr, src, dst);
    recip_kernel<<<gNode, TB>>>();

    // layer 1 (in=2)
    edge1_kernel<<<gEdge4, TB>>>(x, W1);
    node1_kernel<<<gNode4, TB>>>(x, root1, b1, h1);

    // layer 2
    xw_kernel<<<N_NODES / 100, 128>>>(h1, W2);
    edge_gather_kernel<<<gEdge4, TB>>>();
    node16_kernel<<<gNode4, TB>>>(h1, root2, b2, h2);

    // layer 3
    xw_kernel<<<N_NODES / 100, 128>>>(h2, W3);
    edge_gather_kernel<<<gEdge4, TB>>>();
    node16_kernel<<<gNode4, TB>>>(h2, root3, b3, h1);

    final_kernel<<<gNode, TB>>>(h1, fcw, fcb, (float*)d_out);
}

// round 4
// speedup vs baseline: 1.9414x; 1.2272x over previous
#include <cuda_runtime.h>
#include <cuda_fp16.h>
#include <math.h>

#define N_NODES 100000
#define N_EDGES 1600000
#define FULL 0xffffffffu

// ---------------- scratch (static device globals; no allocations) ----------
__device__ float4 g_basis[N_EDGES];              // 4 tensor-product basis vals / edge
__device__ int4   g_meta[N_EDGES];               // {src, dst, packed wi, 0}
__device__ float  g_deg[N_NODES];
__device__ float  g_deginv[N_NODES];
__device__ float4 g_agg[N_NODES * 4];            // [N][16] accumulators
__device__ float4 g_h1[N_NODES * 4];             // hidden ping
__device__ float4 g_h2[N_NODES * 4];             // hidden pong
__device__ uint2  g_xwh[N_NODES * 100];          // [N][25][16] fp16 XW (80MB, L2-resident)

// ---------------- kernels --------------------------------------------------

__global__ void zero_kernel() {
    int i = blockIdx.x * blockDim.x + threadIdx.x;
    if (i < N_NODES * 4) g_agg[i] = make_float4(0.f, 0.f, 0.f, 0.f);
    if (i < N_NODES)     g_deg[i] = 0.f;
}

// basis/knot precompute + degree count (shared across all 3 layers)
__global__ void prep_kernel(const float2* __restrict__ attr,
                            const int* __restrict__ src,
                            const int* __restrict__ dst) {
    int e = blockIdx.x * blockDim.x + threadIdx.x;
    if (e >= N_EDGES) return;
    float2 a = attr[e];
    float v0 = a.x * 4.f, v1 = a.y * 4.f;
    float k0f = fminf(fmaxf(floorf(v0), 0.f), 3.f);
    float k1f = fminf(fmaxf(floorf(v1), 0.f), 3.f);
    float f0 = v0 - k0f, f1 = v1 - k1f;
    int k0 = (int)k0f, k1 = (int)k1f;
    float4 b;
    b.x = (1.f - f0) * (1.f - f1);
    b.y = (1.f - f0) * f1;
    b.z = f0 * (1.f - f1);
    b.w = f0 * f1;
    g_basis[e] = b;
    int j = k0 + 5 * k1;
    int d = dst[e];
    g_meta[e] = make_int4(src[e], d, j | ((j + 5) << 8) | ((j + 1) << 16) | ((j + 6) << 24), 0);
    atomicAdd(&g_deg[d], 1.f);
}

__global__ void recip_kernel() {
    int n = blockIdx.x * blockDim.x + threadIdx.x;
    if (n < N_NODES) g_deginv[n] = 1.f / fmaxf(g_deg[n], 1.f);
}

__device__ __forceinline__ void red_add_v4(float* p, float4 v) {
    asm volatile("red.global.add.v4.f32 [%0], {%1,%2,%3,%4};"
                 :: "l"(p), "f"(v.x), "f"(v.y), "f"(v.z), "f"(v.w) : "memory");
}

__device__ __forceinline__ float2 h2f2(unsigned u) {
    __half2 h = *reinterpret_cast<__half2*>(&u);
    return __half22float2(h);
}

// Layer 1 edge kernel: in=2, 4 threads/edge. W1 in shared as fp16:
// Wsh[w*4+l] = uint4 of 8 halves {W[w][0][4l..4l+3], W[w][1][4l..4l+3]}
// -> ONE LDS.128 per tap (was two).
__global__ void edge1_kernel(const float2* __restrict__ x,
                             const float* __restrict__ W1) {
    __shared__ uint4 Wsh[100];                   // [25][4]
    if (threadIdx.x < 100) {
        int w = threadIdx.x >> 2, l = threadIdx.x & 3;
        const float4* Wv = (const float4*)W1;    // [25][2][4] float4
        float4 a0 = Wv[w * 8 + l];               // W[w][0][4l..4l+3]
        float4 a1 = Wv[w * 8 + 4 + l];           // W[w][1][4l..4l+3]
        __half2 p0 = __floats2half2_rn(a0.x, a0.y);
        __half2 p1 = __floats2half2_rn(a0.z, a0.w);
        __half2 p2 = __floats2half2_rn(a1.x, a1.y);
        __half2 p3 = __floats2half2_rn(a1.z, a1.w);
        uint4 u;
        u.x = *reinterpret_cast<unsigned*>(&p0);
        u.y = *reinterpret_cast<unsigned*>(&p1);
        u.z = *reinterpret_cast<unsigned*>(&p2);
        u.w = *reinterpret_cast<unsigned*>(&p3);
        Wsh[w * 4 + l] = u;
    }
    __syncthreads();
    int t = blockIdx.x * blockDim.x + threadIdx.x;   // E*4 threads exactly
    int lane = threadIdx.x & 31;
    int qb = lane & ~3;
    int l = lane & 3;
    int mc = ((const int*)g_meta)[t];
    float bc = ((const float*)g_basis)[t];
    int s  = __shfl_sync(FULL, mc, qb + 0);
    int d  = __shfl_sync(FULL, mc, qb + 1);
    int wi = __shfl_sync(FULL, mc, qb + 2);
    float bs0 = __shfl_sync(FULL, bc, qb + 0);
    float bs1 = __shfl_sync(FULL, bc, qb + 1);
    float bs2 = __shfl_sync(FULL, bc, qb + 2);
    float bs3 = __shfl_sync(FULL, bc, qb + 3);
    float bs[4] = {bs0, bs1, bs2, bs3};
    float2 xv = x[s];
    float4 acc = make_float4(0.f, 0.f, 0.f, 0.f);
#pragma unroll
    for (int q = 0; q < 4; q++) {
        int w = (wi >> (8 * q)) & 0xff;
        uint4 wv = Wsh[w * 4 + l];
        float2 w00 = h2f2(wv.x), w01 = h2f2(wv.y);
        float2 w10 = h2f2(wv.z), w11 = h2f2(wv.w);
        float c0 = bs[q] * xv.x, c1 = bs[q] * xv.y;
        acc.x += c0 * w00.x + c1 * w10.x;
        acc.y += c0 * w00.y + c1 * w10.y;
        acc.z += c0 * w01.x + c1 * w11.x;
        acc.w += c0 * w01.y + c1 * w11.y;
    }
    red_add_v4((float*)&g_agg[(size_t)d * 4 + l], acc);
}

// XW precompute: block = 128 threads, 100 active as (k,o4); W column register-
// resident, h chunk (100 nodes) staged in shared; fp16 output.
__global__ void xw_kernel(const float4* __restrict__ hin,
                          const float* __restrict__ W) {
    __shared__ float4 hs[400];                   // 100 nodes x 16 floats
    int t = threadIdx.x;
    int n0 = blockIdx.x * 100;
    int k = t >> 2, o4 = t & 3;
    float4 wc[16];
    if (t < 100) {
        const float4* Wv = (const float4*)W;     // [25][16][4]
#pragma unroll
        for (int i = 0; i < 16; i++) wc[i] = Wv[(k * 16 + i) * 4 + o4];
    }
    for (int j = t; j < 400; j += blockDim.x) hs[j] = hin[n0 * 4 + j];
    __syncthreads();
    if (t >= 100) return;
    const float* hsf = (const float*)hs;
    for (int n = 0; n < 100; n++) {
        float4 a = make_float4(0.f, 0.f, 0.f, 0.f);
#pragma unroll
        for (int i = 0; i < 16; i++) {
            float hv = hsf[n * 16 + i];          // warp-broadcast LDS
            a.x += hv * wc[i].x; a.y += hv * wc[i].y;
            a.z += hv * wc[i].z; a.w += hv * wc[i].w;
        }
        __half2 h0 = __floats2half2_rn(a.x, a.y);
        __half2 h1 = __floats2half2_rn(a.z, a.w);
        uint2 u;
        u.x = *reinterpret_cast<unsigned*>(&h0);
        u.y = *reinterpret_cast<unsigned*>(&h1);
        g_xwh[((size_t)(n0 + n) * 25 + k) * 4 + o4] = u;
    }
}

// Edge gather for layers 2/3: 4 threads/edge; per tap the quad loads one
// 32B fp16 row of XW (8B per lane); fp32 accumulate.
__global__ void edge_gather_kernel() {
    int t = blockIdx.x * blockDim.x + threadIdx.x;
    int lane = threadIdx.x & 31;
    int qb = lane & ~3;
    int l = lane & 3;
    int mc = ((const int*)g_meta)[t];
    float bc = ((const float*)g_basis)[t];
    int s  = __shfl_sync(FULL, mc, qb + 0);
    int d  = __shfl_sync(FULL, mc, qb + 1);
    int wi = __shfl_sync(FULL, mc, qb + 2);
    float bs0 = __shfl_sync(FULL, bc, qb + 0);
    float bs1 = __shfl_sync(FULL, bc, qb + 1);
    float bs2 = __shfl_sync(FULL, bc, qb + 2);
    float bs3 = __shfl_sync(FULL, bc, qb + 3);
    float bs[4] = {bs0, bs1, bs2, bs3};
    size_t base = (size_t)s * 100;
    float4 acc = make_float4(0.f, 0.f, 0.f, 0.f);
#pragma unroll
    for (int q = 0; q < 4; q++) {
        int w = (wi >> (8 * q)) & 0xff;
        uint2 v = g_xwh[base + w * 4 + l];
        float2 f0 = h2f2(v.x), f1 = h2f2(v.y);
        float sq = bs[q];
        acc.x += sq * f0.x; acc.y += sq * f0.y;
        acc.z += sq * f1.x; acc.w += sq * f1.y;
    }
    red_add_v4((float*)&g_agg[(size_t)d * 4 + l], acc);
}

// Node update, layer 1 (root: 2x16): h = relu(agg/deg + x@root + b); zero agg.
__global__ void node1_kernel(const float2* __restrict__ x,
                             const float* __restrict__ root,
                             const float* __restrict__ bias,
                             float4* __restrict__ hout) {
    __shared__ float4 rsh[8];
    __shared__ float4 bsh[4];
    if (threadIdx.x < 8)  rsh[threadIdx.x] = ((const float4*)root)[threadIdx.x];
    if (threadIdx.x < 4)  bsh[threadIdx.x] = ((const float4*)bias)[threadIdx.x];
    __syncthreads();
    int t = blockIdx.x * blockDim.x + threadIdx.x;
    int n = t >> 2;
    if (n >= N_NODES) return;
    int l = t & 3;
    float4 a = g_agg[(size_t)n * 4 + l];
    float di = g_deginv[n];
    float2 xv = x[n];
    float4 r0 = rsh[l], r1 = rsh[4 + l], bb = bsh[l];
    float4 o;
    o.x = fmaxf(bb.x + a.x * di + xv.x * r0.x + xv.y * r1.x, 0.f);
    o.y = fmaxf(bb.y + a.y * di + xv.x * r0.y + xv.y * r1.y, 0.f);
    o.z = fmaxf(bb.z + a.z * di + xv.x * r0.z + xv.y * r1.z, 0.f);
    o.w = fmaxf(bb.w + a.w * di + xv.x * r0.w + xv.y * r1.w, 0.f);
    hout[(size_t)n * 4 + l] = o;
    g_agg[(size_t)n * 4 + l] = make_float4(0.f, 0.f, 0.f, 0.f);
}

// Node update, 16-channel root; 4 threads/node.
__global__ void node16_kernel(const float4* __restrict__ hin,
                              const float* __restrict__ root,
                              const float* __restrict__ bias,
                              float4* __restrict__ hout) {
    __shared__ float4 rsh[64];                   // [16][4]
    __shared__ float4 bsh[4];
    for (int j = threadIdx.x; j < 64; j += blockDim.x)
        rsh[j] = ((const float4*)root)[j];
    if (threadIdx.x < 4) bsh[threadIdx.x] = ((const float4*)bias)[threadIdx.x];
    __syncthreads();
    int t = blockIdx.x * blockDim.x + threadIdx.x;
    int n = t >> 2;
    if (n >= N_NODES) return;
    int l = t & 3;
    float4 a = g_agg[(size_t)n * 4 + l];
    float di = g_deginv[n];
    float4 acc = bsh[l];
    acc.x += a.x * di; acc.y += a.y * di; acc.z += a.z * di; acc.w += a.w * di;
    const float* h = (const float*)(hin + (size_t)n * 4);
#pragma unroll
    for (int i = 0; i < 16; i++) {
        float hv = h[i];
        float4 r = rsh[i * 4 + l];
        acc.x += hv * r.x; acc.y += hv * r.y; acc.z += hv * r.z; acc.w += hv * r.w;
    }
    acc.x = fmaxf(acc.x, 0.f); acc.y = fmaxf(acc.y, 0.f);
    acc.z = fmaxf(acc.z, 0.f); acc.w = fmaxf(acc.w, 0.f);
    hout[(size_t)n * 4 + l] = acc;
    g_agg[(size_t)n * 4 + l] = make_float4(0.f, 0.f, 0.f, 0.f);
}

__global__ void final_kernel(const float4* __restrict__ hin,
                             const float* __restrict__ fcw,
                             const float* __restrict__ fcb,
                             float* __restrict__ out) {
    int n = blockIdx.x * blockDim.x + threadIdx.x;
    if (n >= N_NODES) return;
    const float4* h = hin + (size_t)n * 4;
    const float4* w = (const float4*)fcw;
    float z = fcb[0];
#pragma unroll
    for (int j = 0; j < 4; j++) {
        float4 hv = h[j], wv = w[j];
        z += hv.x * wv.x + hv.y * wv.y + hv.z * wv.z + hv.w * wv.w;
    }
    out[n] = 1.f / (1.f + expf(-z));
}

// ---------------- launch ---------------------------------------------------

extern "C" void kernel_launch(void* const* d_in, const int* in_sizes, int n_in,
                              void* d_out, int out_size) {
    const float2* x     = (const float2*)d_in[0];
    const int*    ei    = (const int*)d_in[1];
    const float2* attr  = (const float2*)d_in[2];
    const float*  W1    = (const float*)d_in[3];
    const float*  root1 = (const float*)d_in[4];
    const float*  b1    = (const float*)d_in[5];
    const float*  W2    = (const float*)d_in[6];
    const float*  root2 = (const float*)d_in[7];
    const float*  b2    = (const float*)d_in[8];
    const float*  W3    = (const float*)d_in[9];
    const float*  root3 = (const float*)d_in[10];
    const float*  b3    = (const float*)d_in[11];
    const float*  fcw   = (const float*)d_in[12];
    const float*  fcb   = (const float*)d_in[13];
    const int* src = ei;
    const int* dst = ei + N_EDGES;

    float4 *h1, *h2;
    cudaGetSymbolAddress((void**)&h1, g_h1);
    cudaGetSymbolAddress((void**)&h2, g_h2);

    const int TB = 256;
    int gZero  = (N_NODES * 4 + TB - 1) / TB;
    int gEdge  = (N_EDGES + TB - 1) / TB;
    int gEdge4 = (N_EDGES * 4) / TB;             // exact: 25000
    int gNode4 = (N_NODES * 4 + TB - 1) / TB;
    int gNode  = (N_NODES + TB - 1) / TB;

    zero_kernel<<<gZero, TB>>>();
    prep_kernel<<<gEdge, TB>>>(attr, src, dst);
    recip_kernel<<<gNode, TB>>>();

    // layer 1 (in=2)
    edge1_kernel<<<gEdge4, TB>>>(x, W1);
    node1_kernel<<<gNode4, TB>>>(x, root1, b1, h1);

    // layer 2
    xw_kernel<<<N_NODES / 100, 128>>>(h1, W2);
    edge_gather_kernel<<<gEdge4, TB>>>();
    node16_kernel<<<gNode4, TB>>>(h1, root2, b2, h2);

    // layer 3
    xw_kernel<<<N_NODES / 100, 128>>>(h2, W3);
    edge_gather_kernel<<<gEdge4, TB>>>();
    node16_kernel<<<gNode4, TB>>>(h2, root3, b3, h1);

    final_kernel<<<gNode, TB>>>(h1, fcw, fcb, (float*)d_out);
}